// round 12
// baseline (speedup 1.0000x reference)
#include <cuda_runtime.h>
#include <cstdint>

#define S     4096
#define LC    16
#define CDIM  64
#define CHID  128
#define NDIM  256
#define NHID  512
#define NTAG  64
#define FEAT  384
#define CG    512
#define WG    2048
#define WSEQ_GRID 32

__device__ float d_CPG[(size_t)LC * CG * S];
__device__ float4 d_WPG4[(size_t)NHID * S];   // [t][j] -> float4 of 4 gate pregates
__device__ float d_CHT[(size_t)CHID * S];
__device__ float d_cWhhT[(size_t)CHID * CG];
__device__ float d_HS[(size_t)S * NHID];
// tagged h exchange, replica-minor: word (slot, j, replica) at
// [(slot*512 + j)*32 + replica]. Publish = coalesced 256B; CTA b polls column b.
__device__ unsigned long long d_hp[2 * NHID * WSEQ_GRID];

__device__ __forceinline__ float sigf(float x) {
    return __fdividef(1.f, 1.f + __expf(-x));
}
__device__ __forceinline__ float tanhfast(float x) {
    return 1.f - __fdividef(2.f, __expf(2.f * x) + 1.f);
}
// MUFU tanh (sm_75+): single-op approx, ~1e-4 abs error — fine vs 1e-3 rel threshold
__device__ __forceinline__ float tanha(float x) {
    float y; asm("tanh.approx.f32 %0, %1;" : "=f"(y) : "f"(x)); return y;
}
__device__ __forceinline__ float sigt(float x) {
    return fmaf(0.5f, tanha(0.5f * x), 0.5f);
}

// morally-strong (single-copy atomic) relaxed gpu-scope 8B ops
__device__ __forceinline__ unsigned long long ld_relaxed_u64(const unsigned long long* p) {
    unsigned long long v;
    asm volatile("ld.relaxed.gpu.global.u64 %0, [%1];" : "=l"(v) : "l"(p) : "memory");
    return v;
}
__device__ __forceinline__ void st_relaxed_u64(unsigned long long* p, unsigned long long v) {
    asm volatile("st.relaxed.gpu.global.u64 [%0], %1;" :: "l"(p), "l"(v) : "memory");
}

// char pre-gates + folded init. Blocks (y==0,z==0) reset all d_hp words
// (graph-replay safe) and transpose char Whh.
__global__ void __launch_bounds__(256) k_cpg(
    const float* __restrict__ cemb, const float* __restrict__ cWih,
    const float* __restrict__ cbih, const float* __restrict__ cbhh,
    const int* __restrict__ chars, const float* __restrict__ cWhh)
{
    __shared__ float Ws[128 * CDIM];
    __shared__ float bs[128];
    int tid = threadIdx.x;
    int t = blockIdx.y, gblk = blockIdx.z * 128;

    if (blockIdx.y == 0 && blockIdx.z == 0) {
        int gi = blockIdx.x * 256 + tid;                 // 0..16383
        for (int i = gi; i < 2 * NHID * WSEQ_GRID; i += 64 * 256) {
            // slot = bit 14 of linear index ((slot*512 + j)*32 + r)
            d_hp[i] = ((i >> 14) & 1) ? 0xFFFFFFFE00000000ULL   // slot1: tag -2
                                      : 0xFFFFFFFF00000000ULL;  // slot0: tag -1, h=0
        }
        for (int i = gi; i < CG * CHID; i += 64 * 256) {
            int r = i / CHID, k = i % CHID;
            d_cWhhT[k * CG + r] = cWhh[i];
        }
    }

    for (int i = tid; i < 128 * CDIM; i += 256) Ws[i] = cWih[(size_t)gblk * CDIM + i];
    if (tid < 128) bs[tid] = cbih[gblk + tid] + cbhh[gblk + tid];
    __syncthreads();

    int wl = tid & 63, gq = tid >> 6;
    int w  = blockIdx.x * 64 + wl;
    int ch = chars[w * LC + t];
    float4 e[16];
    const float4* ep = (const float4*)(cemb + (size_t)ch * CDIM);
#pragma unroll
    for (int i = 0; i < 16; i++) e[i] = __ldg(ep + i);

    size_t ob = (size_t)t * CG * S + w;
    for (int gi = 0; gi < 32; gi++) {
        int g = gq * 32 + gi;
        const float4* wp = (const float4*)(Ws + g * CDIM);
        float a = 0.f;
#pragma unroll
        for (int i = 0; i < 16; i++) {
            float4 wv = wp[i];
            a += wv.x * e[i].x + wv.y * e[i].y + wv.z * e[i].z + wv.w * e[i].w;
        }
        d_CPG[ob + (size_t)(gblk + g) * S] = a + bs[g];
    }
}

// char LSTM recurrence: 32 words/CTA, thread=(unit j, half); 16 words/thread
__global__ void __launch_bounds__(256) k_clstm(const int* __restrict__ clens) {
    __shared__ float hs[CHID][36];
    int tid = threadIdx.x, j = tid & 127, half = tid >> 7;
    int w0 = blockIdx.x * 32 + half * 16;

    float c[16]; int le[16];
#pragma unroll
    for (int i = 0; i < 16; i++) { hs[j][half*16+i] = 0.f; c[i] = 0.f; le[i] = clens[w0+i]; }
    __syncthreads();

    for (int t = 0; t < LC; t++) {
        float acc[4][16];
#pragma unroll
        for (int q = 0; q < 4; q++) {
            const float4* pp = (const float4*)(d_CPG + ((size_t)t*CG + q*128 + j)*S + w0);
#pragma unroll
            for (int i4 = 0; i4 < 4; i4++) {
                float4 v = __ldg(pp + i4);
                acc[q][i4*4+0]=v.x; acc[q][i4*4+1]=v.y; acc[q][i4*4+2]=v.z; acc[q][i4*4+3]=v.w;
            }
        }
        const float* wr = d_cWhhT + j;
#pragma unroll 4
        for (int k = 0; k < CHID; k++) {
            float w0q = __ldg(wr + (size_t)k*CG);
            float w1q = __ldg(wr + (size_t)k*CG + 128);
            float w2q = __ldg(wr + (size_t)k*CG + 256);
            float w3q = __ldg(wr + (size_t)k*CG + 384);
            const float* hr = &hs[k][half*16];
#pragma unroll
            for (int i = 0; i < 16; i++) {
                float hv = hr[i];
                acc[0][i] += w0q*hv; acc[1][i] += w1q*hv;
                acc[2][i] += w2q*hv; acc[3][i] += w3q*hv;
            }
        }
        __syncthreads();
#pragma unroll
        for (int i = 0; i < 16; i++) {
            if (t < le[i]) {
                float is = sigf(acc[0][i]), fs = sigf(acc[1][i]);
                float tg = tanhfast(acc[2][i]), os = sigf(acc[3][i]);
                c[i] = fs * c[i] + is * tg;
                hs[j][half*16+i] = os * tanhfast(c[i]);
            }
        }
        __syncthreads();
    }
#pragma unroll
    for (int i = 0; i < 16; i++)
        d_CHT[(size_t)j * S + w0 + i] = hs[j][half*16+i];
}

// word pre-gates: WPG4[t][j] = float4 over gates of Wih[g].feat[t] + bih+bhh
__global__ void __launch_bounds__(256) k_wpg(
    const float* __restrict__ Wih, const float* __restrict__ bih,
    const float* __restrict__ bhh, const float* __restrict__ wemb,
    const int* __restrict__ x)
{
    __shared__ float As[64 * 33];
    __shared__ float Bs[32 * 65];
    __shared__ int   xs[64];
    int tid = threadIdx.x;
    int tbase = blockIdx.x * 64, gbase = blockIdx.y * 64;
    if (tid < 64) xs[tid] = x[tbase + tid];
    int tx = tid & 15, ty = tid >> 4;
    int kkA = tid & 31, giA = tid >> 5;
    float acc[4][4] = {};
    __syncthreads();

    for (int k0 = 0; k0 < FEAT; k0 += 32) {
#pragma unroll
        for (int r = 0; r < 8; r++) {
            int gi = giA + r * 8;
            As[gi * 33 + kkA] = Wih[(size_t)(gbase + gi) * FEAT + k0 + kkA];
        }
        if (k0 < NDIM) {
#pragma unroll
            for (int r = 0; r < 8; r++) {
                int ti = giA + r * 8;
                Bs[kkA * 65 + ti] = __ldg(&wemb[(size_t)xs[ti] * NDIM + k0 + kkA]);
            }
        } else {
            int tt = tid & 63, kk0 = tid >> 6;
#pragma unroll
            for (int r = 0; r < 8; r++) {
                int kk = kk0 + r * 4;
                Bs[kk * 65 + tt] = d_CHT[(size_t)(k0 + kk - NDIM) * S + tbase + tt];
            }
        }
        __syncthreads();
#pragma unroll 8
        for (int kk = 0; kk < 32; kk++) {
            float a[4], b[4];
#pragma unroll
            for (int i = 0; i < 4; i++)  a[i]  = As[(ty*4+i)*33 + kk];
#pragma unroll
            for (int ii = 0; ii < 4; ii++) b[ii] = Bs[kk*65 + tx*4 + ii];
#pragma unroll
            for (int i = 0; i < 4; i++)
#pragma unroll
                for (int ii = 0; ii < 4; ii++) acc[i][ii] += a[i] * b[ii];
        }
        __syncthreads();
    }
#pragma unroll
    for (int i = 0; i < 4; i++) {
        int g = gbase + ty * 4 + i;
        int jj = g & 511, gate = g >> 9;
        float bb = __ldg(&bih[g]) + __ldg(&bhh[g]);
#pragma unroll
        for (int ii = 0; ii < 4; ii++) {
            int t = tbase + tx*4 + ii;
            ((float*)d_WPG4)[(((size_t)t * NHID + jj) << 2) + gate] = acc[i][ii] + bb;
        }
    }
}

// serial word LSTM: 32 CTAs x 512 threads, warp per unit, per-CTA replica-minor
// mailboxes. This round vs R10: pipelined 4-slot poll (sampling ~RT/4), MUFU
// tanh activations, split accumulators. Reduce = shfl butterfly (redux.f32
// does not exist on sm_103 — confirmed by ptxas).
__global__ void __launch_bounds__(512) k_wseq(const float* __restrict__ Whh) {
    __shared__ float smh[2][NHID];
    int tid = threadIdx.x, lane = tid & 31, warp = tid >> 5;
    int j = blockIdx.x * 16 + warp;

    float W[4][16];
#pragma unroll
    for (int q = 0; q < 4; q++) {
        const float4* wp = (const float4*)(Whh + (size_t)(q*NHID + j)*NHID + lane*16);
#pragma unroll
        for (int i4 = 0; i4 < 4; i4++) {
            float4 v = __ldg(wp + i4);
            W[q][i4*4+0]=v.x; W[q][i4*4+1]=v.y; W[q][i4*4+2]=v.z; W[q][i4*4+3]=v.w;
        }
    }
    float c = 0.f;   // redundant per-lane cell state (identical on all lanes)

    for (int t = 0; t < S; t++) {
        // all 4 pregates in one 16B broadcast load, issued before the poll
        float4 pg = __ldg(&d_WPG4[(size_t)t * NHID + j]);

        // pipelined poll: 4 outstanding loads to own mailbox word; sampling
        // period self-balances to ~RT/4 instead of RT
        {
            const unsigned long long* gp =
                d_hp + ((((unsigned)(t & 1) << 9) + tid) << 5) + blockIdx.x;
            unsigned expect = (unsigned)(t - 1);
            unsigned long long q0 = ld_relaxed_u64(gp);
            unsigned long long q1 = ld_relaxed_u64(gp);
            unsigned long long q2 = ld_relaxed_u64(gp);
            unsigned long long q3 = ld_relaxed_u64(gp);
            unsigned long long v;
            for (;;) {
                if ((unsigned)(q0 >> 32) == expect) { v = q0; break; }
                q0 = q1; q1 = q2; q2 = q3;
                q3 = ld_relaxed_u64(gp);
            }
            smh[t & 1][tid] = __int_as_float((int)(unsigned)v);
        }
        __syncthreads();

        // dot with split accumulators (dep depth 8 instead of 16)
        const float4* hv4 = (const float4*)&smh[t & 1][lane * 16];
        float a0=0.f, a1=0.f, a2=0.f, a3=0.f;
        float b0=0.f, b1=0.f, b2=0.f, b3=0.f;
#pragma unroll
        for (int i4 = 0; i4 < 2; i4++) {
            float4 h4 = hv4[i4];
            a0 += W[0][i4*4]*h4.x + W[0][i4*4+1]*h4.y + W[0][i4*4+2]*h4.z + W[0][i4*4+3]*h4.w;
            a1 += W[1][i4*4]*h4.x + W[1][i4*4+1]*h4.y + W[1][i4*4+2]*h4.z + W[1][i4*4+3]*h4.w;
            a2 += W[2][i4*4]*h4.x + W[2][i4*4+1]*h4.y + W[2][i4*4+2]*h4.z + W[2][i4*4+3]*h4.w;
            a3 += W[3][i4*4]*h4.x + W[3][i4*4+1]*h4.y + W[3][i4*4+2]*h4.z + W[3][i4*4+3]*h4.w;
        }
#pragma unroll
        for (int i4 = 2; i4 < 4; i4++) {
            float4 h4 = hv4[i4];
            b0 += W[0][i4*4]*h4.x + W[0][i4*4+1]*h4.y + W[0][i4*4+2]*h4.z + W[0][i4*4+3]*h4.w;
            b1 += W[1][i4*4]*h4.x + W[1][i4*4+1]*h4.y + W[1][i4*4+2]*h4.z + W[1][i4*4+3]*h4.w;
            b2 += W[2][i4*4]*h4.x + W[2][i4*4+1]*h4.y + W[2][i4*4+2]*h4.z + W[2][i4*4+3]*h4.w;
            b3 += W[3][i4*4]*h4.x + W[3][i4*4+1]*h4.y + W[3][i4*4+2]*h4.z + W[3][i4*4+3]*h4.w;
        }
        float g0 = a0 + b0, g1 = a1 + b1, g2 = a2 + b2, g3 = a3 + b3;
#pragma unroll
        for (int off = 16; off > 0; off >>= 1) {
            g0 += __shfl_xor_sync(0xffffffffu, g0, off);
            g1 += __shfl_xor_sync(0xffffffffu, g1, off);
            g2 += __shfl_xor_sync(0xffffffffu, g2, off);
            g3 += __shfl_xor_sync(0xffffffffu, g3, off);
        }

        // all lanes hold full sums -> redundant activations, identical h
        float is = sigt(g0 + pg.x), fs = sigt(g1 + pg.y);
        float tg = tanha(g2 + pg.z), os = sigt(g3 + pg.w);
        c = fs * c + is * tg;
        float h = os * tanha(c);
        unsigned long long pk =
            ((unsigned long long)(unsigned)t << 32) | (unsigned)__float_as_int(h);
        // coalesced publish: lane L -> replica L, consecutive 8B, one 256B burst
        st_relaxed_u64(d_hp + ((((unsigned)((t + 1) & 1) << 9) + j) << 5) + lane, pk);
        if (lane == 0) d_HS[(size_t)t * NHID + j] = h;
    }
}

// logits: out[t][tag] = HS[t].W1[tag] + b1[tag]
__global__ void __launch_bounds__(256) k_logits(
    const float* __restrict__ W1, const float* __restrict__ b1, float* __restrict__ out)
{
    __shared__ float As[64 * 33];
    __shared__ float Bs[64 * 33];
    int tid = threadIdx.x, tbase = blockIdx.x * 64;
    int tx = tid & 15, ty = tid >> 4;
    int kk = tid & 31, r0 = tid >> 5;
    float acc[4][4] = {};

    for (int k0 = 0; k0 < NHID; k0 += 32) {
#pragma unroll
        for (int r = 0; r < 8; r++) {
            int ti = r0 + r * 8;
            As[ti*33 + kk] = d_HS[(size_t)(tbase + ti)*NHID + k0 + kk];
            Bs[ti*33 + kk] = __ldg(&W1[(size_t)ti*NHID + k0 + kk]);
        }
        __syncthreads();
#pragma unroll 8
        for (int k2 = 0; k2 < 32; k2++) {
            float a[4], b[4];
#pragma unroll
            for (int i = 0; i < 4; i++)  a[i]  = As[(ty*4+i)*33 + k2];
#pragma unroll
            for (int ii = 0; ii < 4; ii++) b[ii] = Bs[(tx*4+ii)*33 + k2];
#pragma unroll
            for (int i = 0; i < 4; i++)
#pragma unroll
                for (int ii = 0; ii < 4; ii++) acc[i][ii] += a[i] * b[ii];
        }
        __syncthreads();
    }
#pragma unroll
    for (int i = 0; i < 4; i++) {
        int t = tbase + ty*4 + i;
#pragma unroll
        for (int ii = 0; ii < 4; ii++) {
            int tg = tx*4 + ii;
            out[(size_t)t*NTAG + tg] = acc[i][ii] + __ldg(&b1[tg]);
        }
    }
}

// in-place log-softmax, one warp per row
__global__ void k_lsm(float* __restrict__ out) {
    int warp = threadIdx.x >> 5, lane = threadIdx.x & 31;
    int row = blockIdx.x * 8 + warp;
    float* p = out + (size_t)row * NTAG;
    float v0 = p[lane], v1 = p[lane + 32];
    float m = fmaxf(v0, v1);
#pragma unroll
    for (int off = 16; off > 0; off >>= 1)
        m = fmaxf(m, __shfl_xor_sync(0xffffffffu, m, off));
    float s = __expf(v0 - m) + __expf(v1 - m);
#pragma unroll
    for (int off = 16; off > 0; off >>= 1)
        s += __shfl_xor_sync(0xffffffffu, s, off);
    float ls = m + logf(s);
    p[lane]      = v0 - ls;
    p[lane + 32] = v1 - ls;
}

extern "C" void kernel_launch(void* const* d_in, const int* in_sizes, int n_in,
                              void* d_out, int out_size)
{
    const float* cemb = (const float*)d_in[0];
    const float* cWih = (const float*)d_in[1];
    const float* cWhh = (const float*)d_in[2];
    const float* cbih = (const float*)d_in[3];
    const float* cbhh = (const float*)d_in[4];
    const float* wemb = (const float*)d_in[5];
    const float* Wih  = (const float*)d_in[6];
    const float* Whh  = (const float*)d_in[7];
    const float* bih  = (const float*)d_in[8];
    const float* bhh  = (const float*)d_in[9];
    const float* W1   = (const float*)d_in[10];
    const float* b1   = (const float*)d_in[11];
    const int*   x    = (const int*)d_in[12];
    const int*   chars= (const int*)d_in[13];
    const int*   clens= (const int*)d_in[14];
    float* out = (float*)d_out;

    dim3 gcpg(S / 64, LC, 4);
    k_cpg<<<gcpg, 256>>>(cemb, cWih, cbih, cbhh, chars, cWhh);
    k_clstm<<<S / 32, 256>>>(clens);
    dim3 gwpg(S / 64, WG / 64);
    k_wpg<<<gwpg, 256>>>(Wih, bih, bhh, wemb, x);
    k_wseq<<<WSEQ_GRID, 512>>>(Whh);
    k_logits<<<S / 64, 256>>>(W1, b1, out);
    k_lsm<<<S / 8, 256>>>(out);
}

// round 13
// speedup vs baseline: 1.5097x; 1.5097x over previous
#include <cuda_runtime.h>
#include <cstdint>

#define S     4096
#define LC    16
#define CDIM  64
#define CHID  128
#define NDIM  256
#define NHID  512
#define NTAG  64
#define FEAT  384
#define CG    512
#define WG    2048
#define WSEQ_GRID 32

__device__ float d_CPG[(size_t)LC * CG * S];
__device__ float4 d_WPG4[(size_t)NHID * S];   // [t][j] -> float4 of 4 gate pregates
__device__ float d_CHT[(size_t)CHID * S];
__device__ float d_cWhhT[(size_t)CHID * CG];
__device__ float d_HS[(size_t)S * NHID];
// tagged h exchange, replica-minor: word (slot, j, replica) at
// [(slot*512 + j)*32 + replica]. Publish = coalesced 256B; CTA b polls column b.
__device__ unsigned long long d_hp[2 * NHID * WSEQ_GRID];

__device__ __forceinline__ float sigf(float x) {
    return __fdividef(1.f, 1.f + __expf(-x));
}
__device__ __forceinline__ float tanhfast(float x) {
    return 1.f - __fdividef(2.f, __expf(2.f * x) + 1.f);
}
// MUFU tanh (sm_75+): single-op approx; measured rel_err impact ~1e-6 (R12)
__device__ __forceinline__ float tanha(float x) {
    float y; asm("tanh.approx.f32 %0, %1;" : "=f"(y) : "f"(x)); return y;
}
__device__ __forceinline__ float sigt(float x) {
    return fmaf(0.5f, tanha(0.5f * x), 0.5f);
}

// morally-strong (single-copy atomic) relaxed gpu-scope 8B ops
__device__ __forceinline__ unsigned long long ld_relaxed_u64(const unsigned long long* p) {
    unsigned long long v;
    asm volatile("ld.relaxed.gpu.global.u64 %0, [%1];" : "=l"(v) : "l"(p) : "memory");
    return v;
}
__device__ __forceinline__ void st_relaxed_u64(unsigned long long* p, unsigned long long v) {
    asm volatile("st.relaxed.gpu.global.u64 [%0], %1;" :: "l"(p), "l"(v) : "memory");
}

// char pre-gates + folded init. Blocks (y==0,z==0) reset all d_hp words
// (graph-replay safe) and transpose char Whh.
__global__ void __launch_bounds__(256) k_cpg(
    const float* __restrict__ cemb, const float* __restrict__ cWih,
    const float* __restrict__ cbih, const float* __restrict__ cbhh,
    const int* __restrict__ chars, const float* __restrict__ cWhh)
{
    __shared__ float Ws[128 * CDIM];
    __shared__ float bs[128];
    int tid = threadIdx.x;
    int t = blockIdx.y, gblk = blockIdx.z * 128;

    if (blockIdx.y == 0 && blockIdx.z == 0) {
        int gi = blockIdx.x * 256 + tid;                 // 0..16383
        for (int i = gi; i < 2 * NHID * WSEQ_GRID; i += 64 * 256) {
            // slot = bit 14 of linear index ((slot*512 + j)*32 + r)
            d_hp[i] = ((i >> 14) & 1) ? 0xFFFFFFFE00000000ULL   // slot1: tag -2
                                      : 0xFFFFFFFF00000000ULL;  // slot0: tag -1, h=0
        }
        for (int i = gi; i < CG * CHID; i += 64 * 256) {
            int r = i / CHID, k = i % CHID;
            d_cWhhT[k * CG + r] = cWhh[i];
        }
    }

    for (int i = tid; i < 128 * CDIM; i += 256) Ws[i] = cWih[(size_t)gblk * CDIM + i];
    if (tid < 128) bs[tid] = cbih[gblk + tid] + cbhh[gblk + tid];
    __syncthreads();

    int wl = tid & 63, gq = tid >> 6;
    int w  = blockIdx.x * 64 + wl;
    int ch = chars[w * LC + t];
    float4 e[16];
    const float4* ep = (const float4*)(cemb + (size_t)ch * CDIM);
#pragma unroll
    for (int i = 0; i < 16; i++) e[i] = __ldg(ep + i);

    size_t ob = (size_t)t * CG * S + w;
    for (int gi = 0; gi < 32; gi++) {
        int g = gq * 32 + gi;
        const float4* wp = (const float4*)(Ws + g * CDIM);
        float a = 0.f;
#pragma unroll
        for (int i = 0; i < 16; i++) {
            float4 wv = wp[i];
            a += wv.x * e[i].x + wv.y * e[i].y + wv.z * e[i].z + wv.w * e[i].w;
        }
        d_CPG[ob + (size_t)(gblk + g) * S] = a + bs[g];
    }
}

// char LSTM recurrence: 32 words/CTA, thread=(unit j, half); 16 words/thread
__global__ void __launch_bounds__(256) k_clstm(const int* __restrict__ clens) {
    __shared__ float hs[CHID][36];
    int tid = threadIdx.x, j = tid & 127, half = tid >> 7;
    int w0 = blockIdx.x * 32 + half * 16;

    float c[16]; int le[16];
#pragma unroll
    for (int i = 0; i < 16; i++) { hs[j][half*16+i] = 0.f; c[i] = 0.f; le[i] = clens[w0+i]; }
    __syncthreads();

    for (int t = 0; t < LC; t++) {
        float acc[4][16];
#pragma unroll
        for (int q = 0; q < 4; q++) {
            const float4* pp = (const float4*)(d_CPG + ((size_t)t*CG + q*128 + j)*S + w0);
#pragma unroll
            for (int i4 = 0; i4 < 4; i4++) {
                float4 v = __ldg(pp + i4);
                acc[q][i4*4+0]=v.x; acc[q][i4*4+1]=v.y; acc[q][i4*4+2]=v.z; acc[q][i4*4+3]=v.w;
            }
        }
        const float* wr = d_cWhhT + j;
#pragma unroll 4
        for (int k = 0; k < CHID; k++) {
            float w0q = __ldg(wr + (size_t)k*CG);
            float w1q = __ldg(wr + (size_t)k*CG + 128);
            float w2q = __ldg(wr + (size_t)k*CG + 256);
            float w3q = __ldg(wr + (size_t)k*CG + 384);
            const float* hr = &hs[k][half*16];
#pragma unroll
            for (int i = 0; i < 16; i++) {
                float hv = hr[i];
                acc[0][i] += w0q*hv; acc[1][i] += w1q*hv;
                acc[2][i] += w2q*hv; acc[3][i] += w3q*hv;
            }
        }
        __syncthreads();
#pragma unroll
        for (int i = 0; i < 16; i++) {
            if (t < le[i]) {
                float is = sigf(acc[0][i]), fs = sigf(acc[1][i]);
                float tg = tanhfast(acc[2][i]), os = sigf(acc[3][i]);
                c[i] = fs * c[i] + is * tg;
                hs[j][half*16+i] = os * tanhfast(c[i]);
            }
        }
        __syncthreads();
    }
#pragma unroll
    for (int i = 0; i < 16; i++)
        d_CHT[(size_t)j * S + w0 + i] = hs[j][half*16+i];
}

// word pre-gates: WPG4[t][j] = float4 over gates of Wih[g].feat[t] + bih+bhh
__global__ void __launch_bounds__(256) k_wpg(
    const float* __restrict__ Wih, const float* __restrict__ bih,
    const float* __restrict__ bhh, const float* __restrict__ wemb,
    const int* __restrict__ x)
{
    __shared__ float As[64 * 33];
    __shared__ float Bs[32 * 65];
    __shared__ int   xs[64];
    int tid = threadIdx.x;
    int tbase = blockIdx.x * 64, gbase = blockIdx.y * 64;
    if (tid < 64) xs[tid] = x[tbase + tid];
    int tx = tid & 15, ty = tid >> 4;
    int kkA = tid & 31, giA = tid >> 5;
    float acc[4][4] = {};
    __syncthreads();

    for (int k0 = 0; k0 < FEAT; k0 += 32) {
#pragma unroll
        for (int r = 0; r < 8; r++) {
            int gi = giA + r * 8;
            As[gi * 33 + kkA] = Wih[(size_t)(gbase + gi) * FEAT + k0 + kkA];
        }
        if (k0 < NDIM) {
#pragma unroll
            for (int r = 0; r < 8; r++) {
                int ti = giA + r * 8;
                Bs[kkA * 65 + ti] = __ldg(&wemb[(size_t)xs[ti] * NDIM + k0 + kkA]);
            }
        } else {
            int tt = tid & 63, kk0 = tid >> 6;
#pragma unroll
            for (int r = 0; r < 8; r++) {
                int kk = kk0 + r * 4;
                Bs[kk * 65 + tt] = d_CHT[(size_t)(k0 + kk - NDIM) * S + tbase + tt];
            }
        }
        __syncthreads();
#pragma unroll 8
        for (int kk = 0; kk < 32; kk++) {
            float a[4], b[4];
#pragma unroll
            for (int i = 0; i < 4; i++)  a[i]  = As[(ty*4+i)*33 + kk];
#pragma unroll
            for (int ii = 0; ii < 4; ii++) b[ii] = Bs[kk*65 + tx*4 + ii];
#pragma unroll
            for (int i = 0; i < 4; i++)
#pragma unroll
                for (int ii = 0; ii < 4; ii++) acc[i][ii] += a[i] * b[ii];
        }
        __syncthreads();
    }
#pragma unroll
    for (int i = 0; i < 4; i++) {
        int g = gbase + ty * 4 + i;
        int jj = g & 511, gate = g >> 9;
        float bb = __ldg(&bih[g]) + __ldg(&bhh[g]);
#pragma unroll
        for (int ii = 0; ii < 4; ii++) {
            int t = tbase + tx*4 + ii;
            ((float*)d_WPG4)[(((size_t)t * NHID + jj) << 2) + gate] = acc[i][ii] + bb;
        }
    }
}

// serial word LSTM: 32 CTAs x 512 threads, warp per unit, per-CTA replica-minor
// mailboxes. = R10 + MUFU tanh + split accumulators. Poll is the R10
// single-load loop (R12 proved extra outstanding poll loads poison the LTS
// path shared with the publish stores).
__global__ void __launch_bounds__(512) k_wseq(const float* __restrict__ Whh) {
    __shared__ float smh[2][NHID];
    int tid = threadIdx.x, lane = tid & 31, warp = tid >> 5;
    int j = blockIdx.x * 16 + warp;

    float W[4][16];
#pragma unroll
    for (int q = 0; q < 4; q++) {
        const float4* wp = (const float4*)(Whh + (size_t)(q*NHID + j)*NHID + lane*16);
#pragma unroll
        for (int i4 = 0; i4 < 4; i4++) {
            float4 v = __ldg(wp + i4);
            W[q][i4*4+0]=v.x; W[q][i4*4+1]=v.y; W[q][i4*4+2]=v.z; W[q][i4*4+3]=v.w;
        }
    }
    float c = 0.f;   // redundant per-lane cell state (identical on all lanes)

    for (int t = 0; t < S; t++) {
        // all 4 pregates in one 16B broadcast load, issued before the poll
        float4 pg = __ldg(&d_WPG4[(size_t)t * NHID + j]);

        // single-load poll of own mailbox word (R10 proven)
        {
            const unsigned long long* gp =
                d_hp + ((((unsigned)(t & 1) << 9) + tid) << 5) + blockIdx.x;
            unsigned expect = (unsigned)(t - 1);
            unsigned long long v;
            do { v = ld_relaxed_u64(gp); } while ((unsigned)(v >> 32) != expect);
            smh[t & 1][tid] = __int_as_float((int)(unsigned)v);
        }
        __syncthreads();

        // dot with split accumulators (dep depth 8 instead of 16)
        const float4* hv4 = (const float4*)&smh[t & 1][lane * 16];
        float a0=0.f, a1=0.f, a2=0.f, a3=0.f;
        float b0=0.f, b1=0.f, b2=0.f, b3=0.f;
#pragma unroll
        for (int i4 = 0; i4 < 2; i4++) {
            float4 h4 = hv4[i4];
            a0 += W[0][i4*4]*h4.x + W[0][i4*4+1]*h4.y + W[0][i4*4+2]*h4.z + W[0][i4*4+3]*h4.w;
            a1 += W[1][i4*4]*h4.x + W[1][i4*4+1]*h4.y + W[1][i4*4+2]*h4.z + W[1][i4*4+3]*h4.w;
            a2 += W[2][i4*4]*h4.x + W[2][i4*4+1]*h4.y + W[2][i4*4+2]*h4.z + W[2][i4*4+3]*h4.w;
            a3 += W[3][i4*4]*h4.x + W[3][i4*4+1]*h4.y + W[3][i4*4+2]*h4.z + W[3][i4*4+3]*h4.w;
        }
#pragma unroll
        for (int i4 = 2; i4 < 4; i4++) {
            float4 h4 = hv4[i4];
            b0 += W[0][i4*4]*h4.x + W[0][i4*4+1]*h4.y + W[0][i4*4+2]*h4.z + W[0][i4*4+3]*h4.w;
            b1 += W[1][i4*4]*h4.x + W[1][i4*4+1]*h4.y + W[1][i4*4+2]*h4.z + W[1][i4*4+3]*h4.w;
            b2 += W[2][i4*4]*h4.x + W[2][i4*4+1]*h4.y + W[2][i4*4+2]*h4.z + W[2][i4*4+3]*h4.w;
            b3 += W[3][i4*4]*h4.x + W[3][i4*4+1]*h4.y + W[3][i4*4+2]*h4.z + W[3][i4*4+3]*h4.w;
        }
        float g0 = a0 + b0, g1 = a1 + b1, g2 = a2 + b2, g3 = a3 + b3;
#pragma unroll
        for (int off = 16; off > 0; off >>= 1) {
            g0 += __shfl_xor_sync(0xffffffffu, g0, off);
            g1 += __shfl_xor_sync(0xffffffffu, g1, off);
            g2 += __shfl_xor_sync(0xffffffffu, g2, off);
            g3 += __shfl_xor_sync(0xffffffffu, g3, off);
        }

        // all lanes hold full sums -> redundant activations, identical h
        float is = sigt(g0 + pg.x), fs = sigt(g1 + pg.y);
        float tg = tanha(g2 + pg.z), os = sigt(g3 + pg.w);
        c = fs * c + is * tg;
        float h = os * tanha(c);
        unsigned long long pk =
            ((unsigned long long)(unsigned)t << 32) | (unsigned)__float_as_int(h);
        // coalesced publish: lane L -> replica L, consecutive 8B, one 256B burst
        st_relaxed_u64(d_hp + ((((unsigned)((t + 1) & 1) << 9) + j) << 5) + lane, pk);
        if (lane == 0) d_HS[(size_t)t * NHID + j] = h;
    }
}

// logits: out[t][tag] = HS[t].W1[tag] + b1[tag]
__global__ void __launch_bounds__(256) k_logits(
    const float* __restrict__ W1, const float* __restrict__ b1, float* __restrict__ out)
{
    __shared__ float As[64 * 33];
    __shared__ float Bs[64 * 33];
    int tid = threadIdx.x, tbase = blockIdx.x * 64;
    int tx = tid & 15, ty = tid >> 4;
    int kk = tid & 31, r0 = tid >> 5;
    float acc[4][4] = {};

    for (int k0 = 0; k0 < NHID; k0 += 32) {
#pragma unroll
        for (int r = 0; r < 8; r++) {
            int ti = r0 + r * 8;
            As[ti*33 + kk] = d_HS[(size_t)(tbase + ti)*NHID + k0 + kk];
            Bs[ti*33 + kk] = __ldg(&W1[(size_t)ti*NHID + k0 + kk]);
        }
        __syncthreads();
#pragma unroll 8
        for (int k2 = 0; k2 < 32; k2++) {
            float a[4], b[4];
#pragma unroll
            for (int i = 0; i < 4; i++)  a[i]  = As[(ty*4+i)*33 + k2];
#pragma unroll
            for (int ii = 0; ii < 4; ii++) b[ii] = Bs[(tx*4+ii)*33 + k2];
#pragma unroll
            for (int i = 0; i < 4; i++)
#pragma unroll
                for (int ii = 0; ii < 4; ii++) acc[i][ii] += a[i] * b[ii];
        }
        __syncthreads();
    }
#pragma unroll
    for (int i = 0; i < 4; i++) {
        int t = tbase + ty*4 + i;
#pragma unroll
        for (int ii = 0; ii < 4; ii++) {
            int tg = tx*4 + ii;
            out[(size_t)t*NTAG + tg] = acc[i][ii] + __ldg(&b1[tg]);
        }
    }
}

// in-place log-softmax, one warp per row
__global__ void k_lsm(float* __restrict__ out) {
    int warp = threadIdx.x >> 5, lane = threadIdx.x & 31;
    int row = blockIdx.x * 8 + warp;
    float* p = out + (size_t)row * NTAG;
    float v0 = p[lane], v1 = p[lane + 32];
    float m = fmaxf(v0, v1);
#pragma unroll
    for (int off = 16; off > 0; off >>= 1)
        m = fmaxf(m, __shfl_xor_sync(0xffffffffu, m, off));
    float s = __expf(v0 - m) + __expf(v1 - m);
#pragma unroll
    for (int off = 16; off > 0; off >>= 1)
        s += __shfl_xor_sync(0xffffffffu, s, off);
    float ls = m + logf(s);
    p[lane]      = v0 - ls;
    p[lane + 32] = v1 - ls;
}

extern "C" void kernel_launch(void* const* d_in, const int* in_sizes, int n_in,
                              void* d_out, int out_size)
{
    const float* cemb = (const float*)d_in[0];
    const float* cWih = (const float*)d_in[1];
    const float* cWhh = (const float*)d_in[2];
    const float* cbih = (const float*)d_in[3];
    const float* cbhh = (const float*)d_in[4];
    const float* wemb = (const float*)d_in[5];
    const float* Wih  = (const float*)d_in[6];
    const float* Whh  = (const float*)d_in[7];
    const float* bih  = (const float*)d_in[8];
    const float* bhh  = (const float*)d_in[9];
    const float* W1   = (const float*)d_in[10];
    const float* b1   = (const float*)d_in[11];
    const int*   x    = (const int*)d_in[12];
    const int*   chars= (const int*)d_in[13];
    const int*   clens= (const int*)d_in[14];
    float* out = (float*)d_out;

    dim3 gcpg(S / 64, LC, 4);
    k_cpg<<<gcpg, 256>>>(cemb, cWih, cbih, cbhh, chars, cWhh);
    k_clstm<<<S / 32, 256>>>(clens);
    dim3 gwpg(S / 64, WG / 64);
    k_wpg<<<gwpg, 256>>>(Wih, bih, bhh, wemb, x);
    k_wseq<<<WSEQ_GRID, 512>>>(Whh);
    k_logits<<<S / 64, 256>>>(W1, b1, out);
    k_lsm<<<S / 8, 256>>>(out);
}

// round 14
// speedup vs baseline: 1.7895x; 1.1854x over previous
#include <cuda_runtime.h>
#include <cstdint>

#define S     4096
#define LC    16
#define CDIM  64
#define CHID  128
#define NDIM  256
#define NHID  512
#define NTAG  64
#define FEAT  384
#define CG    512
#define WG    2048
#define WSEQ_GRID 64
#define NREP  64

__device__ float d_CPG[(size_t)LC * CG * S];
__device__ float4 d_WPG4[(size_t)NHID * S];   // [t][j] -> float4 of 4 gate pregates
__device__ float d_CHT[(size_t)CHID * S];
__device__ float d_cWhhT[(size_t)CHID * CG];
__device__ float d_HS[(size_t)S * NHID];
// tagged h exchange, replica-minor, 64 replicas: word (slot, j, replica) at
// [(slot*512 + j)*64 + replica]. Publish = 2 coalesced 256B bursts;
// consumer CTA b polls column b.
__device__ unsigned long long d_hp[2 * NHID * NREP];

__device__ __forceinline__ float sigf(float x) {
    return __fdividef(1.f, 1.f + __expf(-x));
}
__device__ __forceinline__ float tanhfast(float x) {
    return 1.f - __fdividef(2.f, __expf(2.f * x) + 1.f);
}
// MUFU tanh (sm_75+): single-op approx; measured rel_err impact ~1e-6 (R12/R13)
__device__ __forceinline__ float tanha(float x) {
    float y; asm("tanh.approx.f32 %0, %1;" : "=f"(y) : "f"(x)); return y;
}
__device__ __forceinline__ float sigt(float x) {
    return fmaf(0.5f, tanha(0.5f * x), 0.5f);
}

// morally-strong (single-copy atomic) relaxed gpu-scope 8B ops
__device__ __forceinline__ unsigned long long ld_relaxed_u64(const unsigned long long* p) {
    unsigned long long v;
    asm volatile("ld.relaxed.gpu.global.u64 %0, [%1];" : "=l"(v) : "l"(p) : "memory");
    return v;
}
__device__ __forceinline__ void st_relaxed_u64(unsigned long long* p, unsigned long long v) {
    asm volatile("st.relaxed.gpu.global.u64 [%0], %1;" :: "l"(p), "l"(v) : "memory");
}

// char pre-gates + folded init. Blocks (y==0,z==0) reset all d_hp words
// (graph-replay safe) and transpose char Whh.
__global__ void __launch_bounds__(256) k_cpg(
    const float* __restrict__ cemb, const float* __restrict__ cWih,
    const float* __restrict__ cbih, const float* __restrict__ cbhh,
    const int* __restrict__ chars, const float* __restrict__ cWhh)
{
    __shared__ float Ws[128 * CDIM];
    __shared__ float bs[128];
    int tid = threadIdx.x;
    int t = blockIdx.y, gblk = blockIdx.z * 128;

    if (blockIdx.y == 0 && blockIdx.z == 0) {
        int gi = blockIdx.x * 256 + tid;                 // 0..16383
        for (int i = gi; i < 2 * NHID * NREP; i += 64 * 256) {
            // slot = bit 15 of linear index ((slot*512 + j)*64 + r)
            d_hp[i] = ((i >> 15) & 1) ? 0xFFFFFFFE00000000ULL   // slot1: tag -2
                                      : 0xFFFFFFFF00000000ULL;  // slot0: tag -1, h=0
        }
        for (int i = gi; i < CG * CHID; i += 64 * 256) {
            int r = i / CHID, k = i % CHID;
            d_cWhhT[k * CG + r] = cWhh[i];
        }
    }

    for (int i = tid; i < 128 * CDIM; i += 256) Ws[i] = cWih[(size_t)gblk * CDIM + i];
    if (tid < 128) bs[tid] = cbih[gblk + tid] + cbhh[gblk + tid];
    __syncthreads();

    int wl = tid & 63, gq = tid >> 6;
    int w  = blockIdx.x * 64 + wl;
    int ch = chars[w * LC + t];
    float4 e[16];
    const float4* ep = (const float4*)(cemb + (size_t)ch * CDIM);
#pragma unroll
    for (int i = 0; i < 16; i++) e[i] = __ldg(ep + i);

    size_t ob = (size_t)t * CG * S + w;
    for (int gi = 0; gi < 32; gi++) {
        int g = gq * 32 + gi;
        const float4* wp = (const float4*)(Ws + g * CDIM);
        float a = 0.f;
#pragma unroll
        for (int i = 0; i < 16; i++) {
            float4 wv = wp[i];
            a += wv.x * e[i].x + wv.y * e[i].y + wv.z * e[i].z + wv.w * e[i].w;
        }
        d_CPG[ob + (size_t)(gblk + g) * S] = a + bs[g];
    }
}

// char LSTM recurrence: 32 words/CTA, thread=(unit j, half); 16 words/thread
__global__ void __launch_bounds__(256) k_clstm(const int* __restrict__ clens) {
    __shared__ float hs[CHID][36];
    int tid = threadIdx.x, j = tid & 127, half = tid >> 7;
    int w0 = blockIdx.x * 32 + half * 16;

    float c[16]; int le[16];
#pragma unroll
    for (int i = 0; i < 16; i++) { hs[j][half*16+i] = 0.f; c[i] = 0.f; le[i] = clens[w0+i]; }
    __syncthreads();

    for (int t = 0; t < LC; t++) {
        float acc[4][16];
#pragma unroll
        for (int q = 0; q < 4; q++) {
            const float4* pp = (const float4*)(d_CPG + ((size_t)t*CG + q*128 + j)*S + w0);
#pragma unroll
            for (int i4 = 0; i4 < 4; i4++) {
                float4 v = __ldg(pp + i4);
                acc[q][i4*4+0]=v.x; acc[q][i4*4+1]=v.y; acc[q][i4*4+2]=v.z; acc[q][i4*4+3]=v.w;
            }
        }
        const float* wr = d_cWhhT + j;
#pragma unroll 4
        for (int k = 0; k < CHID; k++) {
            float w0q = __ldg(wr + (size_t)k*CG);
            float w1q = __ldg(wr + (size_t)k*CG + 128);
            float w2q = __ldg(wr + (size_t)k*CG + 256);
            float w3q = __ldg(wr + (size_t)k*CG + 384);
            const float* hr = &hs[k][half*16];
#pragma unroll
            for (int i = 0; i < 16; i++) {
                float hv = hr[i];
                acc[0][i] += w0q*hv; acc[1][i] += w1q*hv;
                acc[2][i] += w2q*hv; acc[3][i] += w3q*hv;
            }
        }
        __syncthreads();
#pragma unroll
        for (int i = 0; i < 16; i++) {
            if (t < le[i]) {
                float is = sigf(acc[0][i]), fs = sigf(acc[1][i]);
                float tg = tanhfast(acc[2][i]), os = sigf(acc[3][i]);
                c[i] = fs * c[i] + is * tg;
                hs[j][half*16+i] = os * tanhfast(c[i]);
            }
        }
        __syncthreads();
    }
#pragma unroll
    for (int i = 0; i < 16; i++)
        d_CHT[(size_t)j * S + w0 + i] = hs[j][half*16+i];
}

// word pre-gates: WPG4[t][j] = float4 over gates of Wih[g].feat[t] + bih+bhh
__global__ void __launch_bounds__(256) k_wpg(
    const float* __restrict__ Wih, const float* __restrict__ bih,
    const float* __restrict__ bhh, const float* __restrict__ wemb,
    const int* __restrict__ x)
{
    __shared__ float As[64 * 33];
    __shared__ float Bs[32 * 65];
    __shared__ int   xs[64];
    int tid = threadIdx.x;
    int tbase = blockIdx.x * 64, gbase = blockIdx.y * 64;
    if (tid < 64) xs[tid] = x[tbase + tid];
    int tx = tid & 15, ty = tid >> 4;
    int kkA = tid & 31, giA = tid >> 5;
    float acc[4][4] = {};
    __syncthreads();

    for (int k0 = 0; k0 < FEAT; k0 += 32) {
#pragma unroll
        for (int r = 0; r < 8; r++) {
            int gi = giA + r * 8;
            As[gi * 33 + kkA] = Wih[(size_t)(gbase + gi) * FEAT + k0 + kkA];
        }
        if (k0 < NDIM) {
#pragma unroll
            for (int r = 0; r < 8; r++) {
                int ti = giA + r * 8;
                Bs[kkA * 65 + ti] = __ldg(&wemb[(size_t)xs[ti] * NDIM + k0 + kkA]);
            }
        } else {
            int tt = tid & 63, kk0 = tid >> 6;
#pragma unroll
            for (int r = 0; r < 8; r++) {
                int kk = kk0 + r * 4;
                Bs[kk * 65 + tt] = d_CHT[(size_t)(k0 + kk - NDIM) * S + tbase + tt];
            }
        }
        __syncthreads();
#pragma unroll 8
        for (int kk = 0; kk < 32; kk++) {
            float a[4], b[4];
#pragma unroll
            for (int i = 0; i < 4; i++)  a[i]  = As[(ty*4+i)*33 + kk];
#pragma unroll
            for (int ii = 0; ii < 4; ii++) b[ii] = Bs[kk*65 + tx*4 + ii];
#pragma unroll
            for (int i = 0; i < 4; i++)
#pragma unroll
                for (int ii = 0; ii < 4; ii++) acc[i][ii] += a[i] * b[ii];
        }
        __syncthreads();
    }
#pragma unroll
    for (int i = 0; i < 4; i++) {
        int g = gbase + ty * 4 + i;
        int jj = g & 511, gate = g >> 9;
        float bb = __ldg(&bih[g]) + __ldg(&bhh[g]);
#pragma unroll
        for (int ii = 0; ii < 4; ii++) {
            int t = tbase + tx*4 + ii;
            ((float*)d_WPG4)[(((size_t)t * NHID + jj) << 2) + gate] = acc[i][ii] + bb;
        }
    }
}

// serial word LSTM: 64 CTAs x 256 threads (2 warps/SMSP — halves issue
// arbitration vs 32x512), warp per unit, 64 private replica-minor mailboxes.
// Each thread polls 2 words (distinct words, 1 in-flight load each). Publish =
// 2 coalesced 256B bursts (lane L -> replicas L and L+32).
__global__ void __launch_bounds__(256) k_wseq(const float* __restrict__ Whh) {
    __shared__ float smh[2][NHID];
    int tid = threadIdx.x, lane = tid & 31, warp = tid >> 5;
    int j = blockIdx.x * 8 + warp;

    float W[4][16];
#pragma unroll
    for (int q = 0; q < 4; q++) {
        const float4* wp = (const float4*)(Whh + (size_t)(q*NHID + j)*NHID + lane*16);
#pragma unroll
        for (int i4 = 0; i4 < 4; i4++) {
            float4 v = __ldg(wp + i4);
            W[q][i4*4+0]=v.x; W[q][i4*4+1]=v.y; W[q][i4*4+2]=v.z; W[q][i4*4+3]=v.w;
        }
    }
    float c = 0.f;   // redundant per-lane cell state (identical on all lanes)

    for (int t = 0; t < S; t++) {
        // all 4 pregates in one 16B broadcast load, issued before the poll
        float4 pg = __ldg(&d_WPG4[(size_t)t * NHID + j]);

        // poll 2 distinct words of own replica column (j=tid and j=tid+256)
        {
            unsigned base = ((unsigned)(t & 1) << 9);
            const unsigned long long* gp0 =
                d_hp + (((size_t)(base + tid))       << 6) + blockIdx.x;
            const unsigned long long* gp1 =
                d_hp + (((size_t)(base + tid + 256)) << 6) + blockIdx.x;
            unsigned expect = (unsigned)(t - 1);
            unsigned long long v0, v1;
            do {
                v0 = ld_relaxed_u64(gp0);
                v1 = ld_relaxed_u64(gp1);
            } while ((unsigned)(v0 >> 32) != expect || (unsigned)(v1 >> 32) != expect);
            smh[t & 1][tid]       = __int_as_float((int)(unsigned)v0);
            smh[t & 1][tid + 256] = __int_as_float((int)(unsigned)v1);
        }
        __syncthreads();

        // dot with split accumulators (dep depth 8)
        const float4* hv4 = (const float4*)&smh[t & 1][lane * 16];
        float a0=0.f, a1=0.f, a2=0.f, a3=0.f;
        float b0=0.f, b1=0.f, b2=0.f, b3=0.f;
#pragma unroll
        for (int i4 = 0; i4 < 2; i4++) {
            float4 h4 = hv4[i4];
            a0 += W[0][i4*4]*h4.x + W[0][i4*4+1]*h4.y + W[0][i4*4+2]*h4.z + W[0][i4*4+3]*h4.w;
            a1 += W[1][i4*4]*h4.x + W[1][i4*4+1]*h4.y + W[1][i4*4+2]*h4.z + W[1][i4*4+3]*h4.w;
            a2 += W[2][i4*4]*h4.x + W[2][i4*4+1]*h4.y + W[2][i4*4+2]*h4.z + W[2][i4*4+3]*h4.w;
            a3 += W[3][i4*4]*h4.x + W[3][i4*4+1]*h4.y + W[3][i4*4+2]*h4.z + W[3][i4*4+3]*h4.w;
        }
#pragma unroll
        for (int i4 = 2; i4 < 4; i4++) {
            float4 h4 = hv4[i4];
            b0 += W[0][i4*4]*h4.x + W[0][i4*4+1]*h4.y + W[0][i4*4+2]*h4.z + W[0][i4*4+3]*h4.w;
            b1 += W[1][i4*4]*h4.x + W[1][i4*4+1]*h4.y + W[1][i4*4+2]*h4.z + W[1][i4*4+3]*h4.w;
            b2 += W[2][i4*4]*h4.x + W[2][i4*4+1]*h4.y + W[2][i4*4+2]*h4.z + W[2][i4*4+3]*h4.w;
            b3 += W[3][i4*4]*h4.x + W[3][i4*4+1]*h4.y + W[3][i4*4+2]*h4.z + W[3][i4*4+3]*h4.w;
        }
        float g0 = a0 + b0, g1 = a1 + b1, g2 = a2 + b2, g3 = a3 + b3;
#pragma unroll
        for (int off = 16; off > 0; off >>= 1) {
            g0 += __shfl_xor_sync(0xffffffffu, g0, off);
            g1 += __shfl_xor_sync(0xffffffffu, g1, off);
            g2 += __shfl_xor_sync(0xffffffffu, g2, off);
            g3 += __shfl_xor_sync(0xffffffffu, g3, off);
        }

        // all lanes hold full sums -> redundant activations, identical h
        float is = sigt(g0 + pg.x), fs = sigt(g1 + pg.y);
        float tg = tanha(g2 + pg.z), os = sigt(g3 + pg.w);
        c = fs * c + is * tg;
        float h = os * tanha(c);
        unsigned long long pk =
            ((unsigned long long)(unsigned)t << 32) | (unsigned)__float_as_int(h);
        // publish to all 64 replicas: two coalesced 256B bursts
        unsigned long long* pb =
            d_hp + (((size_t)(((unsigned)((t + 1) & 1) << 9) + j)) << 6);
        st_relaxed_u64(pb + lane, pk);
        st_relaxed_u64(pb + lane + 32, pk);
        if (lane == 0) d_HS[(size_t)t * NHID + j] = h;
    }
}

// logits: out[t][tag] = HS[t].W1[tag] + b1[tag]
__global__ void __launch_bounds__(256) k_logits(
    const float* __restrict__ W1, const float* __restrict__ b1, float* __restrict__ out)
{
    __shared__ float As[64 * 33];
    __shared__ float Bs[64 * 33];
    int tid = threadIdx.x, tbase = blockIdx.x * 64;
    int tx = tid & 15, ty = tid >> 4;
    int kk = tid & 31, r0 = tid >> 5;
    float acc[4][4] = {};

    for (int k0 = 0; k0 < NHID; k0 += 32) {
#pragma unroll
        for (int r = 0; r < 8; r++) {
            int ti = r0 + r * 8;
            As[ti*33 + kk] = d_HS[(size_t)(tbase + ti)*NHID + k0 + kk];
            Bs[ti*33 + kk] = __ldg(&W1[(size_t)ti*NHID + k0 + kk]);
        }
        __syncthreads();
#pragma unroll 8
        for (int k2 = 0; k2 < 32; k2++) {
            float a[4], b[4];
#pragma unroll
            for (int i = 0; i < 4; i++)  a[i]  = As[(ty*4+i)*33 + k2];
#pragma unroll
            for (int ii = 0; ii < 4; ii++) b[ii] = Bs[(tx*4+ii)*33 + k2];
#pragma unroll
            for (int i = 0; i < 4; i++)
#pragma unroll
                for (int ii = 0; ii < 4; ii++) acc[i][ii] += a[i] * b[ii];
        }
        __syncthreads();
    }
#pragma unroll
    for (int i = 0; i < 4; i++) {
        int t = tbase + ty*4 + i;
#pragma unroll
        for (int ii = 0; ii < 4; ii++) {
            int tg = tx*4 + ii;
            out[(size_t)t*NTAG + tg] = acc[i][ii] + __ldg(&b1[tg]);
        }
    }
}

// in-place log-softmax, one warp per row
__global__ void k_lsm(float* __restrict__ out) {
    int warp = threadIdx.x >> 5, lane = threadIdx.x & 31;
    int row = blockIdx.x * 8 + warp;
    float* p = out + (size_t)row * NTAG;
    float v0 = p[lane], v1 = p[lane + 32];
    float m = fmaxf(v0, v1);
#pragma unroll
    for (int off = 16; off > 0; off >>= 1)
        m = fmaxf(m, __shfl_xor_sync(0xffffffffu, m, off));
    float s = __expf(v0 - m) + __expf(v1 - m);
#pragma unroll
    for (int off = 16; off > 0; off >>= 1)
        s += __shfl_xor_sync(0xffffffffu, s, off);
    float ls = m + logf(s);
    p[lane]      = v0 - ls;
    p[lane + 32] = v1 - ls;
}

extern "C" void kernel_launch(void* const* d_in, const int* in_sizes, int n_in,
                              void* d_out, int out_size)
{
    const float* cemb = (const float*)d_in[0];
    const float* cWih = (const float*)d_in[1];
    const float* cWhh = (const float*)d_in[2];
    const float* cbih = (const float*)d_in[3];
    const float* cbhh = (const float*)d_in[4];
    const float* wemb = (const float*)d_in[5];
    const float* Wih  = (const float*)d_in[6];
    const float* Whh  = (const float*)d_in[7];
    const float* bih  = (const float*)d_in[8];
    const float* bhh  = (const float*)d_in[9];
    const float* W1   = (const float*)d_in[10];
    const float* b1   = (const float*)d_in[11];
    const int*   x    = (const int*)d_in[12];
    const int*   chars= (const int*)d_in[13];
    const int*   clens= (const int*)d_in[14];
    float* out = (float*)d_out;

    dim3 gcpg(S / 64, LC, 4);
    k_cpg<<<gcpg, 256>>>(cemb, cWih, cbih, cbhh, chars, cWhh);
    k_clstm<<<S / 32, 256>>>(clens);
    dim3 gwpg(S / 64, WG / 64);
    k_wpg<<<gwpg, 256>>>(Wih, bih, bhh, wemb, x);
    k_wseq<<<WSEQ_GRID, 256>>>(Whh);
    k_logits<<<S / 64, 256>>>(W1, b1, out);
    k_lsm<<<S / 8, 256>>>(out);
}